// round 4
// baseline (speedup 1.0000x reference)
#include <cuda_runtime.h>
#include <math.h>

#define NBATCH 8
#define NPTS   131072
#define NGRP   30
#define NGB    (NBATCH*NGRP)   // 240
#define KNN    100
#define STRIDE 4369            // 131072/30
#define HB     2048            // float-radix bins: bits(d2) >> 21
#define SVCAP  2048            // survivor cap (expected ~700)
#define SUBCAP 1024
#define GPT    6               // groups per tile
#define GT     5               // tiles (GT*GPT = NGRP)
#define PTC    8               // point chunks
#define CHUNK  (NPTS/PTC)      // 16384
#define NT     256
#define MTGT   700.0f          // target expected survivors per group

// fallback (proven exact path) caps
#define FCAP   6144
#define FSCAP  512
#define FB_DYN (4*FCAP*4)

#define SEL_DYN ((5*SVCAP + HB)*4)

// -------- static device scratch (no allocation allowed) --------
__device__ float    d_Ta[NGB];
__device__ unsigned d_nsv[NGB];
__device__ int      d_flag[NGB];
__device__ float4   d_sv[NGB][SVCAP];
__device__ double   d_gmean[NGB][3];
__device__ double   d_gcov[NGB][6];
__device__ float    d_dirs[NGB][3];
__device__ double   d_fs[NGB];

__device__ __forceinline__ unsigned d2bin(float d2) {
    return __float_as_uint(d2) >> 21;
}

// ===========================================================================
// prep: per-group analytic radius with expected MTGT points inside.
// Distance s from query q (|q|=rho) to X~N(0,I3) has density
//   f(s) = s/(rho*sqrt(2pi)) * (exp(-(s-rho)^2/2) - exp(-(s+rho)^2/2))
// Integrate upward until NPTS*P >= MTGT. Overshoot is safe (more survivors);
// all hazards are flag-guarded with an exact fallback.
// ===========================================================================
__global__ void prep_kernel(const float* __restrict__ pts_all) {
    int t = threadIdx.x;
    if (t >= NGB) return;
    d_nsv[t] = 0u;
    d_flag[t] = 0;
    int b = t / NGRP, g = t % NGRP;
    int ci = g * STRIDE;
    const float* pts = pts_all + (size_t)b * NPTS * 3;
    float qx = pts[3*ci], qy = pts[3*ci+1], qz = pts[3*ci+2];
    float rho = sqrtf(qx*qx + qy*qy + qz*qz);
    rho = fmaxf(rho, 0.02f);
    const float A = (float)NPTS * 0.3989422804014327f / rho; // NPTS/(sqrt(2pi)*rho)
    float cum = 0.0f;
    float ds = 0.015f;
    float s = 0.5f * ds;
    float r = 8.0f;
    for (int it = 0; it < 540; it++) {
        float em = expf(-0.5f*(s-rho)*(s-rho)) - expf(-0.5f*(s+rho)*(s+rho));
        cum += A * s * em * ds;
        if (cum >= MTGT) { r = s + 0.5f*ds; break; }
        s += ds;
    }
    d_Ta[t] = r * r;
}

// ===========================================================================
// scan: one pass over the points; each block = (batch, 6-group tile, chunk).
// Push survivors (d2 to group center < Ta) into global per-group buffers.
// ===========================================================================
__global__ void __launch_bounds__(NT) scan_kernel(const float* __restrict__ pts_all) {
    int bidx = blockIdx.x;
    int pc = bidx % PTC;
    int gt = (bidx / PTC) % GT;
    int b  = bidx / (PTC * GT);
    const float* __restrict__ pts = pts_all + (size_t)b * NPTS * 3;
    const float4* __restrict__ p4 = (const float4*)pts;
    const int gbase = b * NGRP + gt * GPT;

    float qx[GPT], qy[GPT], qz[GPT], ta[GPT];
    #pragma unroll
    for (int j = 0; j < GPT; j++) {
        int ci = (gt*GPT + j) * STRIDE;
        qx[j] = pts[3*ci]; qy[j] = pts[3*ci+1]; qz[j] = pts[3*ci+2];
        ta[j] = d_Ta[gbase + j];
    }

    const int q0 = pc * (CHUNK/4);
    for (int it = q0 + threadIdx.x; it < q0 + CHUNK/4; it += NT) {
        float4 A = p4[3*it+0];
        float4 B = p4[3*it+1];
        float4 C = p4[3*it+2];
        float xs[4] = {A.x, A.w, B.z, C.y};
        float ys[4] = {A.y, B.x, B.w, C.z};
        float zs[4] = {A.z, B.y, C.x, C.w};
        #pragma unroll
        for (int k = 0; k < 4; k++) {
            #pragma unroll
            for (int j = 0; j < GPT; j++) {
                float dx = xs[k]-qx[j], dy = ys[k]-qy[j], dz = zs[k]-qz[j];
                float d2 = fmaf(dx, dx, fmaf(dy, dy, dz*dz));
                if (d2 < ta[j]) {
                    unsigned s = atomicAdd(&d_nsv[gbase + j], 1u);
                    if (s < SVCAP)
                        d_sv[gbase + j][s] = make_float4(xs[k], ys[k], zs[k],
                                                         __int_as_float(4*it + k));
                }
            }
        }
    }
}

// ===========================================================================
// select: per-group, both KNN passes over the (smem-resident) survivor set.
// ===========================================================================
struct SelSh {
    unsigned partial[NT];
    int      subSlot[SUBCAP];
    int      order[KNN];
    double   red[NT];
    float    q2s[4];
    unsigned nsub;
    int      pivotS;
    int      bflag;
};

__device__ __forceinline__ double tree_red(double* red, int tid, double v) {
    red[tid] = v;
    __syncthreads();
    #pragma unroll
    for (int s = NT/2; s > 0; s >>= 1) {
        if (tid < s) red[tid] += red[tid + s];
        __syncthreads();
    }
    double r = red[0];
    __syncthreads();
    return r;
}

// exact top-KNN rank selection over sd/si[0..S): fills order[0..KNN).
// returns false on subset overflow (caller must flag + fallback).
__device__ __forceinline__ bool select_topk(const float* sd, const int* si,
                                            unsigned* hist, SelSh* sh,
                                            int S, int tid) {
    for (int i = tid; i < HB; i += NT) hist[i] = 0u;
    if (tid == 0) sh->nsub = 0u;
    __syncthreads();
    for (int s = tid; s < S; s += NT) atomicAdd(&hist[d2bin(sd[s])], 1u);
    __syncthreads();
    {
        unsigned ps = 0;
        #pragma unroll
        for (int j = 0; j < HB/NT; j++) ps += hist[tid*(HB/NT) + j];
        sh->partial[tid] = ps;
    }
    __syncthreads();
    if (tid == 0) {
        unsigned c = 0; int t = 0;
        while (c + sh->partial[t] < KNN) { c += sh->partial[t]; t++; }
        int bin = t * (HB/NT);
        while (c + hist[bin] < KNN) { c += hist[bin]; bin++; }
        sh->pivotS = bin;
    }
    __syncthreads();
    const unsigned piv = (unsigned)sh->pivotS;
    for (int s = tid; s < S; s += NT) {
        if (d2bin(sd[s]) <= piv) {
            unsigned u = atomicAdd(&sh->nsub, 1u);
            if (u < SUBCAP) sh->subSlot[u] = s;
        }
    }
    __syncthreads();
    if (sh->nsub > SUBCAP) return false;
    const int U = (int)sh->nsub;
    for (int u = tid; u < U; u += NT) {
        int slot = sh->subSlot[u];
        float d = sd[slot]; int id = si[slot];
        int rank = 0;
        for (int v = 0; v < U; v++) {
            int s2 = sh->subSlot[v];
            float dv = sd[s2];
            rank += (dv < d) || (dv == d && si[s2] < id);
        }
        if (rank < KNN) sh->order[rank] = slot;
    }
    __syncthreads();
    return true;
}

__global__ void __launch_bounds__(NT) select_kernel(const float* __restrict__ pts_all) {
    extern __shared__ float dyn[];
    float* sx = dyn;
    float* sy = sx + SVCAP;
    float* sz = sy + SVCAP;
    float* sd = sz + SVCAP;
    int*   si = (int*)(sd + SVCAP);
    unsigned* hist = (unsigned*)(si + SVCAP);
    __shared__ SelSh sh;

    const int tid = threadIdx.x;
    const int gb  = blockIdx.x;

    unsigned Sfull = d_nsv[gb];
    if (Sfull > SVCAP || Sfull < KNN) {
        if (tid == 0) d_flag[gb] = 1;
        return;
    }
    const int S = (int)Sfull;
    const int b = gb / NGRP, g = gb % NGRP;
    const int ci = g * STRIDE;
    const float* __restrict__ pts = pts_all + (size_t)b * NPTS * 3;
    const float qx = pts[3*ci], qy = pts[3*ci+1], qz = pts[3*ci+2];
    const float Ta = d_Ta[gb];

    // load survivors; d2 vs center (identical expression as scan)
    for (int s = tid; s < S; s += NT) {
        float4 v = d_sv[gb][s];
        sx[s] = v.x; sy[s] = v.y; sz[s] = v.z;
        si[s] = __float_as_int(v.w);
        float dx = v.x - qx, dy = v.y - qy, dz = v.z - qz;
        sd[s] = fmaf(dx, dx, fmaf(dy, dy, dz*dz));
    }
    __syncthreads();

    // ---- pass 1 ----
    if (!select_topk(sd, si, hist, &sh, S, tid)) {
        if (tid == 0) d_flag[gb] = 1;
        return;
    }
    double vx = (tid < KNN) ? (double)sx[sh.order[tid]] : 0.0;
    double vy = (tid < KNN) ? (double)sy[sh.order[tid]] : 0.0;
    double vz = (tid < KNN) ? (double)sz[sh.order[tid]] : 0.0;
    double mx = tree_red(sh.red, tid, vx) / (double)KNN;
    double my = tree_red(sh.red, tid, vy) / (double)KNN;
    double mz = tree_red(sh.red, tid, vz) / (double)KNN;
    if (tid == 0) {
        d_gmean[gb][0] = mx; d_gmean[gb][1] = my; d_gmean[gb][2] = mz;
        float edge1 = __uint_as_float(((unsigned)sh.pivotS + 1u) << 21);
        double dxq = mx - (double)qx, dyq = my - (double)qy, dzq = mz - (double)qz;
        double D  = sqrt(dxq*dxq + dyq*dyq + dzq*dzq);
        double r1 = sqrt((double)edge1);
        double R  = 2.0*D + r1;
        float T2  = (float)(R*R) * 1.0002f;
        sh.q2s[0] = (float)mx; sh.q2s[1] = (float)my; sh.q2s[2] = (float)mz;
        sh.q2s[3] = T2;
        sh.bflag = (T2 > Ta) ? 1 : 0;      // pass-2 ball must fit inside Ta ball
        if (sh.bflag) d_flag[gb] = 1;
    }
    __syncthreads();
    if (sh.bflag) return;

    // ---- pass 2: distances vs mean query ----
    const float mxf = sh.q2s[0], myf = sh.q2s[1], mzf = sh.q2s[2];
    __syncthreads();
    for (int s = tid; s < S; s += NT) {
        float dx = sx[s]-mxf, dy = sy[s]-myf, dz = sz[s]-mzf;
        sd[s] = fmaf(dx, dx, fmaf(dy, dy, dz*dz));
    }
    __syncthreads();
    if (!select_topk(sd, si, hist, &sh, S, tid)) {
        if (tid == 0) d_flag[gb] = 1;
        return;
    }
    double X = (tid < KNN) ? (double)sx[sh.order[tid]] : 0.0;
    double Y = (tid < KNN) ? (double)sy[sh.order[tid]] : 0.0;
    double Z = (tid < KNN) ? (double)sz[sh.order[tid]] : 0.0;
    double s0 = tree_red(sh.red, tid, X);
    double s1 = tree_red(sh.red, tid, Y);
    double s2 = tree_red(sh.red, tid, Z);
    double s3 = tree_red(sh.red, tid, X*X);
    double s4 = tree_red(sh.red, tid, X*Y);
    double s5 = tree_red(sh.red, tid, X*Z);
    double s6 = tree_red(sh.red, tid, Y*Y);
    double s7 = tree_red(sh.red, tid, Y*Z);
    double s8 = tree_red(sh.red, tid, Z*Z);
    if (tid == 0) {
        const double K = (double)KNN;
        double ax = s0/K, ay = s1/K, az = s2/K;
        d_gcov[gb][0] = s3/K - ax*ax;
        d_gcov[gb][1] = s4/K - ax*ay;
        d_gcov[gb][2] = s5/K - ax*az;
        d_gcov[gb][3] = s6/K - ay*ay;
        d_gcov[gb][4] = s7/K - ay*az;
        d_gcov[gb][5] = s8/K - az*az;
    }
}

// ===========================================================================
// fallback: exact brute-force (R2 path), only for flagged groups.
// ===========================================================================
__global__ void __launch_bounds__(NT, 2) fb_kernel(const float* __restrict__ pts_all) {
    const int gb = blockIdx.x;
    if (d_flag[gb] == 0) return;

    extern __shared__ float dyn[];
    float* cX = dyn;
    float* cY = cX + FCAP;
    float* cZ = cY + FCAP;
    int*   cI = (int*)(cZ + FCAP);

    __shared__ unsigned hist[HB];
    __shared__ unsigned partial[NT];
    __shared__ float    subD[FSCAP];
    __shared__ int      subI[FSCAP];
    __shared__ int      subSlot[FSCAP];
    __shared__ int      order[KNN];
    __shared__ unsigned ncand, nsub;
    __shared__ int      pivotS;
    __shared__ float    bc[4];

    const int tid = threadIdx.x;
    const int b   = gb / NGRP;
    const int g   = gb % NGRP;
    const float* __restrict__ pts = pts_all + (size_t)b * NPTS * 3;
    const float4* __restrict__ p4 = (const float4*)pts;

    const int c0 = g * STRIDE;
    const float qx = pts[3*c0+0], qy = pts[3*c0+1], qz = pts[3*c0+2];

    // scan 1: full histogram
    for (int i = tid; i < HB; i += NT) hist[i] = 0u;
    __syncthreads();
    for (int it = tid; it < NPTS/4; it += NT) {
        float4 A = p4[3*it+0], B = p4[3*it+1], C = p4[3*it+2];
        float xs[4] = {A.x, A.w, B.z, C.y};
        float ys[4] = {A.y, B.x, B.w, C.z};
        float zs[4] = {A.z, B.y, C.x, C.w};
        #pragma unroll
        for (int k = 0; k < 4; k++) {
            float dx = xs[k]-qx, dy = ys[k]-qy, dz = zs[k]-qz;
            float d2 = fmaf(dx, dx, fmaf(dy, dy, dz*dz));
            atomicAdd(&hist[d2bin(d2)], 1u);
        }
    }
    __syncthreads();
    {
        unsigned ps = 0;
        #pragma unroll
        for (int j = 0; j < HB/NT; j++) ps += hist[tid*(HB/NT) + j];
        partial[tid] = ps;
    }
    __syncthreads();
    if (tid == 0) {
        unsigned c = 0; int t = 0;
        while (c + partial[t] < KNN) { c += partial[t]; t++; }
        int bin = t * (HB/NT);
        while (c + hist[bin] < KNN) { c += hist[bin]; bin++; }
        pivotS = bin;
    }
    __syncthreads();
    const float edge1 = __uint_as_float(((unsigned)pivotS + 1u) << 21);

    // scan 2: collect C1
    if (tid == 0) ncand = 0u;
    __syncthreads();
    for (int it = tid; it < NPTS/4; it += NT) {
        float4 A = p4[3*it+0], B = p4[3*it+1], C = p4[3*it+2];
        float xs[4] = {A.x, A.w, B.z, C.y};
        float ys[4] = {A.y, B.x, B.w, C.z};
        float zs[4] = {A.z, B.y, C.x, C.w};
        #pragma unroll
        for (int k = 0; k < 4; k++) {
            float dx = xs[k]-qx, dy = ys[k]-qy, dz = zs[k]-qz;
            float d2 = fmaf(dx, dx, fmaf(dy, dy, dz*dz));
            if (d2 < edge1) {
                unsigned s = atomicAdd(&ncand, 1u);
                if (s < FSCAP) {
                    cX[s] = xs[k]; cY[s] = ys[k]; cZ[s] = zs[k];
                    subD[s] = d2; subI[s] = 4*it + k;
                }
            }
        }
    }
    __syncthreads();
    {
        int S = (int)min(ncand, (unsigned)FSCAP);
        for (int s = tid; s < S; s += NT) {
            float d = subD[s]; int id = subI[s];
            int rank = 0;
            for (int j = 0; j < S; j++) {
                float dj = subD[j];
                rank += (dj < d) || (dj == d && subI[j] < id);
            }
            if (rank < KNN) order[rank] = s;
        }
    }
    __syncthreads();
    if (tid == 0) {
        double sxa = 0.0, sya = 0.0, sza = 0.0;
        for (int r = 0; r < KNN; r++) {
            int s = order[r];
            sxa += (double)cX[s]; sya += (double)cY[s]; sza += (double)cZ[s];
        }
        double mx = sxa/(double)KNN, my = sya/(double)KNN, mz = sza/(double)KNN;
        d_gmean[gb][0] = mx; d_gmean[gb][1] = my; d_gmean[gb][2] = mz;
        double dxq = mx - (double)qx, dyq = my - (double)qy, dzq = mz - (double)qz;
        double D  = sqrt(dxq*dxq + dyq*dyq + dzq*dzq);
        double r1 = sqrt((double)edge1);
        double R  = 2.0*D + r1;
        bc[0] = (float)mx; bc[1] = (float)my; bc[2] = (float)mz;
        bc[3] = (float)(R*R) * 1.0002f;
    }
    __syncthreads();
    const float q2x = bc[0], q2y = bc[1], q2z = bc[2];
    const float T2  = bc[3];

    // scan 3: collect C2 ball
    if (tid == 0) ncand = 0u;
    __syncthreads();
    for (int it = tid; it < NPTS/4; it += NT) {
        float4 A = p4[3*it+0], B = p4[3*it+1], C = p4[3*it+2];
        float xs[4] = {A.x, A.w, B.z, C.y};
        float ys[4] = {A.y, B.x, B.w, C.z};
        float zs[4] = {A.z, B.y, C.x, C.w};
        #pragma unroll
        for (int k = 0; k < 4; k++) {
            float dx = xs[k]-qx, dy = ys[k]-qy, dz = zs[k]-qz;
            float d2 = fmaf(dx, dx, fmaf(dy, dy, dz*dz));
            if (d2 < T2) {
                unsigned s = atomicAdd(&ncand, 1u);
                if (s < FCAP) {
                    cX[s] = xs[k]; cY[s] = ys[k]; cZ[s] = zs[k];
                    cI[s] = 4*it + k;
                }
            }
        }
    }
    __syncthreads();
    const int C2 = (int)min(ncand, (unsigned)FCAP);

    for (int i = tid; i < HB; i += NT) hist[i] = 0u;
    __syncthreads();
    for (int c = tid; c < C2; c += NT) {
        float dx = cX[c]-q2x, dy = cY[c]-q2y, dz = cZ[c]-q2z;
        atomicAdd(&hist[d2bin(fmaf(dx, dx, fmaf(dy, dy, dz*dz)))], 1u);
    }
    __syncthreads();
    {
        unsigned ps = 0;
        #pragma unroll
        for (int j = 0; j < HB/NT; j++) ps += hist[tid*(HB/NT) + j];
        partial[tid] = ps;
    }
    __syncthreads();
    if (tid == 0) {
        unsigned c = 0; int t = 0;
        while (c + partial[t] < KNN) { c += partial[t]; t++; }
        int bin = t * (HB/NT);
        while (c + hist[bin] < KNN) { c += hist[bin]; bin++; }
        pivotS = bin;
        nsub = 0u;
    }
    __syncthreads();
    const unsigned piv2 = (unsigned)pivotS;
    for (int c = tid; c < C2; c += NT) {
        float dx = cX[c]-q2x, dy = cY[c]-q2y, dz = cZ[c]-q2z;
        float d2 = fmaf(dx, dx, fmaf(dy, dy, dz*dz));
        if (d2bin(d2) <= piv2) {
            unsigned s = atomicAdd(&nsub, 1u);
            if (s < FSCAP) { subD[s] = d2; subI[s] = cI[c]; subSlot[s] = c; }
        }
    }
    __syncthreads();
    {
        int S = (int)min(nsub, (unsigned)FSCAP);
        for (int s = tid; s < S; s += NT) {
            float d = subD[s]; int id = subI[s];
            int rank = 0;
            for (int j = 0; j < S; j++) {
                float dj = subD[j];
                rank += (dj < d) || (dj == d && subI[j] < id);
            }
            if (rank < KNN) order[rank] = subSlot[s];
        }
    }
    __syncthreads();
    if (tid == 0) {
        double s0=0,s1=0,s2=0,s3=0,s4=0,s5=0,s6=0,s7=0,s8=0;
        for (int r = 0; r < KNN; r++) {
            int c = order[r];
            double X = (double)cX[c], Y = (double)cY[c], Z = (double)cZ[c];
            s0 += X; s1 += Y; s2 += Z;
            s3 += X*X; s4 += X*Y; s5 += X*Z;
            s6 += Y*Y; s7 += Y*Z; s8 += Z*Z;
        }
        const double K = (double)KNN;
        double mx = s0/K, my = s1/K, mz = s2/K;
        d_gcov[gb][0] = s3/K - mx*mx;
        d_gcov[gb][1] = s4/K - mx*my;
        d_gcov[gb][2] = s5/K - mx*mz;
        d_gcov[gb][3] = s6/K - my*my;
        d_gcov[gb][4] = s7/K - my*mz;
        d_gcov[gb][5] = s8/K - mz*mz;
    }
}

// ===========================================================================
// eig: 240 parallel 3x3 symmetric eigensolves (double, analytic).
// ===========================================================================
__global__ void eig_kernel() {
    if (threadIdx.x != 0) return;
    const int t = blockIdx.x;

    double a00 = d_gcov[t][0], a01 = d_gcov[t][1], a02 = d_gcov[t][2];
    double a11 = d_gcov[t][3], a12 = d_gcov[t][4], a22 = d_gcov[t][5];

    double q  = (a00 + a11 + a22) / 3.0;
    double p1 = a01*a01 + a02*a02 + a12*a12;
    double b00 = a00 - q, b11 = a11 - q, b22 = a22 - q;
    double p2 = b00*b00 + b11*b11 + b22*b22 + 2.0*p1;
    double l1, l2, l3;
    if (p2 < 1e-60) {
        l1 = l2 = l3 = q;
    } else {
        double p  = sqrt(p2 / 6.0);
        double ip = 1.0 / p;
        double c00 = b00*ip, c11 = b11*ip, c22 = b22*ip;
        double c01 = a01*ip, c02 = a02*ip, c12 = a12*ip;
        double detB = c00*(c11*c22 - c12*c12)
                    - c01*(c01*c22 - c12*c02)
                    + c02*(c01*c12 - c11*c02);
        double r = 0.5 * detB;
        r = fmin(1.0, fmax(-1.0, r));
        double phi = (double)acosf((float)r) * (1.0/3.0);
        l3 = q + 2.0*p*(double)cosf((float)phi);
        l1 = q + 2.0*p*(double)cosf((float)(phi + 2.0943951023931953));
        l2 = 3.0*q - l1 - l3;
    }
    double denom = l1 + l2 + l3 + 1e-9;
    d_fs[t] = (l3 - l2) / denom;

    double r0x = a00 - l3, r0y = a01,      r0z = a02;
    double r1x = a01,      r1y = a11 - l3, r1z = a12;
    double r2x = a02,      r2y = a12,      r2z = a22 - l3;
    double vax = r0y*r1z - r0z*r1y, vay = r0z*r1x - r0x*r1z, vaz = r0x*r1y - r0y*r1x;
    double vbx = r1y*r2z - r1z*r2y, vby = r1z*r2x - r1x*r2z, vbz = r1x*r2y - r1y*r2x;
    double vcx = r2y*r0z - r2z*r0y, vcy = r2z*r0x - r2x*r0z, vcz = r2x*r0y - r2y*r0x;
    double na = vax*vax + vay*vay + vaz*vaz;
    double nb = vbx*vbx + vby*vby + vbz*vbz;
    double nc = vcx*vcx + vcy*vcy + vcz*vcz;
    double vx, vy, vz, nn;
    if (na >= nb && na >= nc) { vx = vax; vy = vay; vz = vaz; nn = na; }
    else if (nb >= nc)        { vx = vbx; vy = vby; vz = vbz; nn = nb; }
    else                      { vx = vcx; vy = vcy; vz = vcz; nn = nc; }
    if (nn < 1e-300) { vx = 0.0; vy = 0.0; vz = 1.0; nn = 1.0; }
    double inn = rsqrt(nn);
    d_dirs[t][0] = (float)(vx * inn);
    d_dirs[t][1] = (float)(vy * inn);
    d_dirs[t][2] = (float)(vz * inn);
}

// ===========================================================================
// out: nearest-group argmin + final reductions.
// ===========================================================================
__global__ void __launch_bounds__(256) out_kernel(float* __restrict__ out) {
    __shared__ float  dirs[NGB][3];
    __shared__ float  gmf[NGB][3];
    __shared__ double redd[256];
    const int t = threadIdx.x;

    double fs = 0.0;
    if (t < NGB) {
        fs = d_fs[t];
        dirs[t][0] = d_dirs[t][0];
        dirs[t][1] = d_dirs[t][1];
        dirs[t][2] = d_dirs[t][2];
        gmf[t][0] = (float)d_gmean[t][0];
        gmf[t][1] = (float)d_gmean[t][1];
        gmf[t][2] = (float)d_gmean[t][2];
    }
    __syncthreads();

    double term = 0.0;
    if (t < NGB) {
        int b = t / NGRP, g = t % NGRP;
        float qx = gmf[t][0], qy = gmf[t][1], qz = gmf[t][2];
        float best = 3.4e38f; int bj = 0;
        for (int o = 0; o < NGRP; o++) {
            float dx = qx - gmf[b*NGRP+o][0];
            float dy = qy - gmf[b*NGRP+o][1];
            float dz = qz - gmf[b*NGRP+o][2];
            float dd = dx*dx + dy*dy + dz*dz;
            if (o == g) dd += 1e30f;
            if (dd < best) { best = dd; bj = o; }
        }
        int j = b*NGRP + bj;
        float cs = dirs[t][0]*dirs[j][0] + dirs[t][1]*dirs[j][1] + dirs[t][2]*dirs[j][2];
        term = 1.0 - (double)cs * (double)cs;
    }

    redd[t] = fs;
    __syncthreads();
    for (int s = 128; s > 0; s >>= 1) { if (t < s) redd[t] += redd[t+s]; __syncthreads(); }
    double sumfs = redd[0];
    __syncthreads();
    redd[t] = term;
    __syncthreads();
    for (int s = 128; s > 0; s >>= 1) { if (t < s) redd[t] += redd[t+s]; __syncthreads(); }
    double sumterm = redd[0];

    if (t == 0) out[0] = (float)(-sumfs / (double)NBATCH + sumterm / (double)NGB);
}

extern "C" void kernel_launch(void* const* d_in, const int* in_sizes, int n_in,
                              void* d_out, int out_size) {
    const float* pts = (const float*)d_in[0];
    float* out = (float*)d_out;
    cudaFuncSetAttribute(select_kernel, cudaFuncAttributeMaxDynamicSharedMemorySize, SEL_DYN);
    cudaFuncSetAttribute(fb_kernel, cudaFuncAttributeMaxDynamicSharedMemorySize, FB_DYN);
    prep_kernel<<<1, 256>>>(pts);
    scan_kernel<<<NBATCH*GT*PTC, NT>>>(pts);
    select_kernel<<<NGB, NT, SEL_DYN>>>(pts);
    fb_kernel<<<NGB, NT, FB_DYN>>>(pts);
    eig_kernel<<<NGB, 32>>>();
    out_kernel<<<1, 256>>>(out);
}

// round 5
// speedup vs baseline: 2.4565x; 2.4565x over previous
#include <cuda_runtime.h>
#include <math.h>

#define NBATCH 8
#define NPTS   131072
#define NGRP   30
#define NGB    (NBATCH*NGRP)   // 240
#define KNN    100
#define STRIDE 4369            // 131072/30
#define HB     2048            // float-radix bins: bits(d2) >> 21
#define SVCAP  2048            // survivor cap (expected ~700)
#define RCAP   4096            // rescue-ball cap
#define SUBCAP 1024
#define GPT    6               // groups per tile
#define GT     5               // tiles (GT*GPT = NGRP)
#define PTC    8               // point chunks
#define CHUNK  (NPTS/PTC)      // 16384
#define NT     256
#define MTGT   700.0f          // target expected survivors per group

// brute fallback (proven exact path) caps — should never fire
#define FCAP   6144
#define FSCAP  512
#define FB_DYN (4*FCAP*4)

#define SEL_DYN ((5*SVCAP + HB)*4)
#define RES_DYN ((5*RCAP  + HB)*4)

// -------- static device scratch (no allocation allowed) --------
__device__ float    d_Ta[NGB];
__device__ unsigned d_nsv[NGB];
__device__ unsigned d_nsv2[NGB];
__device__ int      d_flag[NGB];        // 0 ok, 1 rescue pass-2, 2 brute
__device__ float    d_T2[NGB];
__device__ float    d_meanf[NGB][3];
__device__ float4   d_sv[NGB][SVCAP];
__device__ float4   d_sv2[NGB][RCAP];
__device__ double   d_gmean[NGB][3];
__device__ double   d_gcov[NGB][6];
__device__ float    d_dirs[NGB][3];
__device__ double   d_fs[NGB];

__device__ __forceinline__ unsigned d2bin(float d2) {
    return __float_as_uint(d2) >> 21;
}

// ===========================================================================
// prep: per-group analytic radius with expected MTGT points inside.
// ===========================================================================
__global__ void prep_kernel(const float* __restrict__ pts_all) {
    int t = threadIdx.x;
    if (t >= NGB) return;
    d_nsv[t] = 0u;
    d_nsv2[t] = 0u;
    d_flag[t] = 0;
    int b = t / NGRP, g = t % NGRP;
    int ci = g * STRIDE;
    const float* pts = pts_all + (size_t)b * NPTS * 3;
    float qx = pts[3*ci], qy = pts[3*ci+1], qz = pts[3*ci+2];
    float rho = sqrtf(qx*qx + qy*qy + qz*qz);
    rho = fmaxf(rho, 0.02f);
    const float A = (float)NPTS * 0.3989422804014327f / rho;
    float cum = 0.0f;
    float ds = 0.015f;
    float s = 0.5f * ds;
    float r = 8.0f;
    for (int it = 0; it < 540; it++) {
        float em = expf(-0.5f*(s-rho)*(s-rho)) - expf(-0.5f*(s+rho)*(s+rho));
        cum += A * s * em * ds;
        if (cum >= MTGT) { r = s + 0.5f*ds; break; }
        s += ds;
    }
    d_Ta[t] = r * r;
}

// ===========================================================================
// scan: one pass; each block = (batch, 6-group tile, chunk). Push survivors.
// ===========================================================================
__global__ void __launch_bounds__(NT) scan_kernel(const float* __restrict__ pts_all) {
    int bidx = blockIdx.x;
    int pc = bidx % PTC;
    int gt = (bidx / PTC) % GT;
    int b  = bidx / (PTC * GT);
    const float* __restrict__ pts = pts_all + (size_t)b * NPTS * 3;
    const float4* __restrict__ p4 = (const float4*)pts;
    const int gbase = b * NGRP + gt * GPT;

    float qx[GPT], qy[GPT], qz[GPT], ta[GPT];
    #pragma unroll
    for (int j = 0; j < GPT; j++) {
        int ci = (gt*GPT + j) * STRIDE;
        qx[j] = pts[3*ci]; qy[j] = pts[3*ci+1]; qz[j] = pts[3*ci+2];
        ta[j] = d_Ta[gbase + j];
    }

    const int q0 = pc * (CHUNK/4);
    for (int it = q0 + threadIdx.x; it < q0 + CHUNK/4; it += NT) {
        float4 A = p4[3*it+0];
        float4 B = p4[3*it+1];
        float4 C = p4[3*it+2];
        float xs[4] = {A.x, A.w, B.z, C.y};
        float ys[4] = {A.y, B.x, B.w, C.z};
        float zs[4] = {A.z, B.y, C.x, C.w};
        #pragma unroll
        for (int k = 0; k < 4; k++) {
            #pragma unroll
            for (int j = 0; j < GPT; j++) {
                float dx = xs[k]-qx[j], dy = ys[k]-qy[j], dz = zs[k]-qz[j];
                float d2 = fmaf(dx, dx, fmaf(dy, dy, dz*dz));
                if (d2 < ta[j]) {
                    unsigned s = atomicAdd(&d_nsv[gbase + j], 1u);
                    if (s < SVCAP)
                        d_sv[gbase + j][s] = make_float4(xs[k], ys[k], zs[k],
                                                         __int_as_float(4*it + k));
                }
            }
        }
    }
}

// ===========================================================================
// shared selection machinery
// ===========================================================================
struct SelSh {
    unsigned partial[NT];
    int      subSlot[SUBCAP];
    int      order[KNN];
    double   red[NT];
    float    q2s[4];
    double   Dc;
    unsigned nsub;
    int      pivotS;
    int      bflag;
};

__device__ __forceinline__ double tree_red(double* red, int tid, double v) {
    red[tid] = v;
    __syncthreads();
    #pragma unroll
    for (int s = NT/2; s > 0; s >>= 1) {
        if (tid < s) red[tid] += red[tid + s];
        __syncthreads();
    }
    double r = red[0];
    __syncthreads();
    return r;
}

__device__ __forceinline__ bool select_topk(const float* sd, const int* si,
                                            unsigned* hist, SelSh* sh,
                                            int S, int tid) {
    for (int i = tid; i < HB; i += NT) hist[i] = 0u;
    if (tid == 0) sh->nsub = 0u;
    __syncthreads();
    for (int s = tid; s < S; s += NT) atomicAdd(&hist[d2bin(sd[s])], 1u);
    __syncthreads();
    {
        unsigned ps = 0;
        #pragma unroll
        for (int j = 0; j < HB/NT; j++) ps += hist[tid*(HB/NT) + j];
        sh->partial[tid] = ps;
    }
    __syncthreads();
    if (tid == 0) {
        unsigned c = 0; int t = 0;
        while (c + sh->partial[t] < KNN) { c += sh->partial[t]; t++; }
        int bin = t * (HB/NT);
        while (c + hist[bin] < KNN) { c += hist[bin]; bin++; }
        sh->pivotS = bin;
    }
    __syncthreads();
    const unsigned piv = (unsigned)sh->pivotS;
    for (int s = tid; s < S; s += NT) {
        if (d2bin(sd[s]) <= piv) {
            unsigned u = atomicAdd(&sh->nsub, 1u);
            if (u < SUBCAP) sh->subSlot[u] = s;
        }
    }
    __syncthreads();
    if (sh->nsub > SUBCAP) return false;
    const int U = (int)sh->nsub;
    for (int u = tid; u < U; u += NT) {
        int slot = sh->subSlot[u];
        float d = sd[slot]; int id = si[slot];
        int rank = 0;
        for (int v = 0; v < U; v++) {
            int s2 = sh->subSlot[v];
            float dv = sd[s2];
            rank += (dv < d) || (dv == d && si[s2] < id);
        }
        if (rank < KNN) sh->order[rank] = slot;
    }
    __syncthreads();
    return true;
}

// covariance accumulation from order[] and store
__device__ __forceinline__ void cov_store(const float* sx, const float* sy,
                                          const float* sz, SelSh* sh,
                                          int tid, int gb) {
    double X = (tid < KNN) ? (double)sx[sh->order[tid]] : 0.0;
    double Y = (tid < KNN) ? (double)sy[sh->order[tid]] : 0.0;
    double Z = (tid < KNN) ? (double)sz[sh->order[tid]] : 0.0;
    double s0 = tree_red(sh->red, tid, X);
    double s1 = tree_red(sh->red, tid, Y);
    double s2 = tree_red(sh->red, tid, Z);
    double s3 = tree_red(sh->red, tid, X*X);
    double s4 = tree_red(sh->red, tid, X*Y);
    double s5 = tree_red(sh->red, tid, X*Z);
    double s6 = tree_red(sh->red, tid, Y*Y);
    double s7 = tree_red(sh->red, tid, Y*Z);
    double s8 = tree_red(sh->red, tid, Z*Z);
    if (tid == 0) {
        const double K = (double)KNN;
        double ax = s0/K, ay = s1/K, az = s2/K;
        d_gcov[gb][0] = s3/K - ax*ax;
        d_gcov[gb][1] = s4/K - ax*ay;
        d_gcov[gb][2] = s5/K - ax*az;
        d_gcov[gb][3] = s6/K - ay*ay;
        d_gcov[gb][4] = s7/K - ay*az;
        d_gcov[gb][5] = s8/K - az*az;
    }
}

// ===========================================================================
// select: per-group, pass-1 always; pass-2 in place when the tight ball test
// proves coverage, else flag for the parallel rescue.
// ===========================================================================
__global__ void __launch_bounds__(NT) select_kernel(const float* __restrict__ pts_all) {
    extern __shared__ float dyn[];
    float* sx = dyn;
    float* sy = sx + SVCAP;
    float* sz = sy + SVCAP;
    float* sd = sz + SVCAP;
    int*   si = (int*)(sd + SVCAP);
    unsigned* hist = (unsigned*)(si + SVCAP);
    __shared__ SelSh sh;

    const int tid = threadIdx.x;
    const int gb  = blockIdx.x;

    unsigned Sfull = d_nsv[gb];
    if (Sfull > SVCAP || Sfull < KNN) {
        if (tid == 0) d_flag[gb] = 2;
        return;
    }
    const int S = (int)Sfull;
    const int b = gb / NGRP, g = gb % NGRP;
    const int ci = g * STRIDE;
    const float* __restrict__ pts = pts_all + (size_t)b * NPTS * 3;
    const float qx = pts[3*ci], qy = pts[3*ci+1], qz = pts[3*ci+2];
    const float Ta = d_Ta[gb];

    for (int s = tid; s < S; s += NT) {
        float4 v = d_sv[gb][s];
        sx[s] = v.x; sy[s] = v.y; sz[s] = v.z;
        si[s] = __float_as_int(v.w);
        float dx = v.x - qx, dy = v.y - qy, dz = v.z - qz;
        sd[s] = fmaf(dx, dx, fmaf(dy, dy, dz*dz));
    }
    __syncthreads();

    // ---- pass 1 (survivors = ALL points < Ta, so exact) ----
    if (!select_topk(sd, si, hist, &sh, S, tid)) {
        if (tid == 0) d_flag[gb] = 2;
        return;
    }
    double vx = (tid < KNN) ? (double)sx[sh.order[tid]] : 0.0;
    double vy = (tid < KNN) ? (double)sy[sh.order[tid]] : 0.0;
    double vz = (tid < KNN) ? (double)sz[sh.order[tid]] : 0.0;
    double mx = tree_red(sh.red, tid, vx) / (double)KNN;
    double my = tree_red(sh.red, tid, vy) / (double)KNN;
    double mz = tree_red(sh.red, tid, vz) / (double)KNN;
    if (tid == 0) {
        d_gmean[gb][0] = mx; d_gmean[gb][1] = my; d_gmean[gb][2] = mz;
        float fmx = (float)mx, fmy = (float)my, fmz = (float)mz;
        d_meanf[gb][0] = fmx; d_meanf[gb][1] = fmy; d_meanf[gb][2] = fmz;
        double dxq = (double)fmx - (double)qx;
        double dyq = (double)fmy - (double)qy;
        double dzq = (double)fmz - (double)qz;
        sh.Dc = sqrt(dxq*dxq + dyq*dyq + dzq*dzq);
        sh.q2s[0] = fmx; sh.q2s[1] = fmy; sh.q2s[2] = fmz;
    }
    __syncthreads();

    // ---- pass 2 attempt over survivors ----
    const float mxf = sh.q2s[0], myf = sh.q2s[1], mzf = sh.q2s[2];
    __syncthreads();
    for (int s = tid; s < S; s += NT) {
        float dx = sx[s]-mxf, dy = sy[s]-myf, dz = sz[s]-mzf;
        sd[s] = fmaf(dx, dx, fmaf(dy, dy, dz*dz));
    }
    __syncthreads();
    if (!select_topk(sd, si, hist, &sh, S, tid)) {
        if (tid == 0) d_flag[gb] = 2;
        return;
    }
    if (tid == 0) {
        // tight upper bound on the true pass-2 100-NN distance
        float d100 = sd[sh.order[KNN-1]];
        double lhs = sh.Dc + sqrt((double)d100);
        if (lhs*lhs*(1.0 + 1e-4) < (double)Ta) {
            sh.bflag = 0;
        } else {
            sh.bflag = 1;
            d_flag[gb] = 1;
            d_T2[gb] = d100;     // rescue-ball radius^2 (inclusive)
        }
    }
    __syncthreads();
    if (sh.bflag) return;

    cov_store(sx, sy, sz, &sh, tid, gb);
}

// ===========================================================================
// rescue scan: parallel over chunks; collect ball {d2(mean) <= T2'}.
// ===========================================================================
__global__ void __launch_bounds__(NT) rescue_scan_kernel(const float* __restrict__ pts_all) {
    const int gb = blockIdx.x / PTC;
    if (d_flag[gb] != 1) return;
    const int pc = blockIdx.x % PTC;
    const int b = gb / NGRP;
    const float* __restrict__ pts = pts_all + (size_t)b * NPTS * 3;
    const float4* __restrict__ p4 = (const float4*)pts;
    const float mxf = d_meanf[gb][0], myf = d_meanf[gb][1], mzf = d_meanf[gb][2];
    const float T2 = d_T2[gb];

    const int q0 = pc * (CHUNK/4);
    for (int it = q0 + threadIdx.x; it < q0 + CHUNK/4; it += NT) {
        float4 A = p4[3*it+0];
        float4 B = p4[3*it+1];
        float4 C = p4[3*it+2];
        float xs[4] = {A.x, A.w, B.z, C.y};
        float ys[4] = {A.y, B.x, B.w, C.z};
        float zs[4] = {A.z, B.y, C.x, C.w};
        #pragma unroll
        for (int k = 0; k < 4; k++) {
            float dx = xs[k]-mxf, dy = ys[k]-myf, dz = zs[k]-mzf;
            float d2 = fmaf(dx, dx, fmaf(dy, dy, dz*dz));
            if (d2 <= T2) {
                unsigned s = atomicAdd(&d_nsv2[gb], 1u);
                if (s < RCAP)
                    d_sv2[gb][s] = make_float4(xs[k], ys[k], zs[k],
                                               __int_as_float(4*it + k));
            }
        }
    }
}

// ===========================================================================
// rescue select: exact pass-2 over the rescue ball.
// ===========================================================================
__global__ void __launch_bounds__(NT) rescue_select_kernel() {
    const int gb = blockIdx.x;
    if (d_flag[gb] != 1) return;

    extern __shared__ float dyn[];
    float* sx = dyn;
    float* sy = sx + RCAP;
    float* sz = sy + RCAP;
    float* sd = sz + RCAP;
    int*   si = (int*)(sd + RCAP);
    unsigned* hist = (unsigned*)(si + RCAP);
    __shared__ SelSh sh;

    const int tid = threadIdx.x;
    unsigned S2u = d_nsv2[gb];
    if (S2u > RCAP || S2u < KNN) {
        if (tid == 0) d_flag[gb] = 2;
        return;
    }
    const int S = (int)S2u;
    const float mxf = d_meanf[gb][0], myf = d_meanf[gb][1], mzf = d_meanf[gb][2];

    for (int s = tid; s < S; s += NT) {
        float4 v = d_sv2[gb][s];
        sx[s] = v.x; sy[s] = v.y; sz[s] = v.z;
        si[s] = __float_as_int(v.w);
        float dx = v.x - mxf, dy = v.y - myf, dz = v.z - mzf;
        sd[s] = fmaf(dx, dx, fmaf(dy, dy, dz*dz));
    }
    __syncthreads();
    if (!select_topk(sd, si, hist, &sh, S, tid)) {
        if (tid == 0) d_flag[gb] = 2;
        return;
    }
    cov_store(sx, sy, sz, &sh, tid, gb);
}

// ===========================================================================
// brute fallback (flag==2 only; should never fire)
// ===========================================================================
__global__ void __launch_bounds__(NT, 2) fb_kernel(const float* __restrict__ pts_all) {
    const int gb = blockIdx.x;
    if (d_flag[gb] != 2) return;

    extern __shared__ float dyn[];
    float* cX = dyn;
    float* cY = cX + FCAP;
    float* cZ = cY + FCAP;
    int*   cI = (int*)(cZ + FCAP);

    __shared__ unsigned hist[HB];
    __shared__ unsigned partial[NT];
    __shared__ float    subD[FSCAP];
    __shared__ int      subI[FSCAP];
    __shared__ int      subSlot[FSCAP];
    __shared__ int      order[KNN];
    __shared__ unsigned ncand, nsub;
    __shared__ int      pivotS;
    __shared__ float    bc[4];

    const int tid = threadIdx.x;
    const int b   = gb / NGRP;
    const int g   = gb % NGRP;
    const float* __restrict__ pts = pts_all + (size_t)b * NPTS * 3;
    const float4* __restrict__ p4 = (const float4*)pts;

    const int c0 = g * STRIDE;
    const float qx = pts[3*c0+0], qy = pts[3*c0+1], qz = pts[3*c0+2];

    for (int i = tid; i < HB; i += NT) hist[i] = 0u;
    __syncthreads();
    for (int it = tid; it < NPTS/4; it += NT) {
        float4 A = p4[3*it+0], B = p4[3*it+1], C = p4[3*it+2];
        float xs[4] = {A.x, A.w, B.z, C.y};
        float ys[4] = {A.y, B.x, B.w, C.z};
        float zs[4] = {A.z, B.y, C.x, C.w};
        #pragma unroll
        for (int k = 0; k < 4; k++) {
            float dx = xs[k]-qx, dy = ys[k]-qy, dz = zs[k]-qz;
            atomicAdd(&hist[d2bin(fmaf(dx, dx, fmaf(dy, dy, dz*dz)))], 1u);
        }
    }
    __syncthreads();
    {
        unsigned ps = 0;
        #pragma unroll
        for (int j = 0; j < HB/NT; j++) ps += hist[tid*(HB/NT) + j];
        partial[tid] = ps;
    }
    __syncthreads();
    if (tid == 0) {
        unsigned c = 0; int t = 0;
        while (c + partial[t] < KNN) { c += partial[t]; t++; }
        int bin = t * (HB/NT);
        while (c + hist[bin] < KNN) { c += hist[bin]; bin++; }
        pivotS = bin;
    }
    __syncthreads();
    const float edge1 = __uint_as_float(((unsigned)pivotS + 1u) << 21);

    if (tid == 0) ncand = 0u;
    __syncthreads();
    for (int it = tid; it < NPTS/4; it += NT) {
        float4 A = p4[3*it+0], B = p4[3*it+1], C = p4[3*it+2];
        float xs[4] = {A.x, A.w, B.z, C.y};
        float ys[4] = {A.y, B.x, B.w, C.z};
        float zs[4] = {A.z, B.y, C.x, C.w};
        #pragma unroll
        for (int k = 0; k < 4; k++) {
            float dx = xs[k]-qx, dy = ys[k]-qy, dz = zs[k]-qz;
            float d2 = fmaf(dx, dx, fmaf(dy, dy, dz*dz));
            if (d2 < edge1) {
                unsigned s = atomicAdd(&ncand, 1u);
                if (s < FSCAP) {
                    cX[s] = xs[k]; cY[s] = ys[k]; cZ[s] = zs[k];
                    subD[s] = d2; subI[s] = 4*it + k;
                }
            }
        }
    }
    __syncthreads();
    {
        int S = (int)min(ncand, (unsigned)FSCAP);
        for (int s = tid; s < S; s += NT) {
            float d = subD[s]; int id = subI[s];
            int rank = 0;
            for (int j = 0; j < S; j++) {
                float dj = subD[j];
                rank += (dj < d) || (dj == d && subI[j] < id);
            }
            if (rank < KNN) order[rank] = s;
        }
    }
    __syncthreads();
    if (tid == 0) {
        double sxa = 0.0, sya = 0.0, sza = 0.0;
        for (int r = 0; r < KNN; r++) {
            int s = order[r];
            sxa += (double)cX[s]; sya += (double)cY[s]; sza += (double)cZ[s];
        }
        double mx = sxa/(double)KNN, my = sya/(double)KNN, mz = sza/(double)KNN;
        d_gmean[gb][0] = mx; d_gmean[gb][1] = my; d_gmean[gb][2] = mz;
        double dxq = mx - (double)qx, dyq = my - (double)qy, dzq = mz - (double)qz;
        double D  = sqrt(dxq*dxq + dyq*dyq + dzq*dzq);
        double r1 = sqrt((double)edge1);
        double R  = 2.0*D + r1;
        bc[0] = (float)mx; bc[1] = (float)my; bc[2] = (float)mz;
        bc[3] = (float)(R*R) * 1.0002f;
    }
    __syncthreads();
    const float q2x = bc[0], q2y = bc[1], q2z = bc[2];
    const float T2  = bc[3];

    if (tid == 0) ncand = 0u;
    __syncthreads();
    for (int it = tid; it < NPTS/4; it += NT) {
        float4 A = p4[3*it+0], B = p4[3*it+1], C = p4[3*it+2];
        float xs[4] = {A.x, A.w, B.z, C.y};
        float ys[4] = {A.y, B.x, B.w, C.z};
        float zs[4] = {A.z, B.y, C.x, C.w};
        #pragma unroll
        for (int k = 0; k < 4; k++) {
            float dx = xs[k]-qx, dy = ys[k]-qy, dz = zs[k]-qz;
            float d2 = fmaf(dx, dx, fmaf(dy, dy, dz*dz));
            if (d2 < T2) {
                unsigned s = atomicAdd(&ncand, 1u);
                if (s < FCAP) {
                    cX[s] = xs[k]; cY[s] = ys[k]; cZ[s] = zs[k];
                    cI[s] = 4*it + k;
                }
            }
        }
    }
    __syncthreads();
    const int C2 = (int)min(ncand, (unsigned)FCAP);

    for (int i = tid; i < HB; i += NT) hist[i] = 0u;
    __syncthreads();
    for (int c = tid; c < C2; c += NT) {
        float dx = cX[c]-q2x, dy = cY[c]-q2y, dz = cZ[c]-q2z;
        atomicAdd(&hist[d2bin(fmaf(dx, dx, fmaf(dy, dy, dz*dz)))], 1u);
    }
    __syncthreads();
    {
        unsigned ps = 0;
        #pragma unroll
        for (int j = 0; j < HB/NT; j++) ps += hist[tid*(HB/NT) + j];
        partial[tid] = ps;
    }
    __syncthreads();
    if (tid == 0) {
        unsigned c = 0; int t = 0;
        while (c + partial[t] < KNN) { c += partial[t]; t++; }
        int bin = t * (HB/NT);
        while (c + hist[bin] < KNN) { c += hist[bin]; bin++; }
        pivotS = bin;
        nsub = 0u;
    }
    __syncthreads();
    const unsigned piv2 = (unsigned)pivotS;
    for (int c = tid; c < C2; c += NT) {
        float dx = cX[c]-q2x, dy = cY[c]-q2y, dz = cZ[c]-q2z;
        float d2 = fmaf(dx, dx, fmaf(dy, dy, dz*dz));
        if (d2bin(d2) <= piv2) {
            unsigned s = atomicAdd(&nsub, 1u);
            if (s < FSCAP) { subD[s] = d2; subI[s] = cI[c]; subSlot[s] = c; }
        }
    }
    __syncthreads();
    {
        int S = (int)min(nsub, (unsigned)FSCAP);
        for (int s = tid; s < S; s += NT) {
            float d = subD[s]; int id = subI[s];
            int rank = 0;
            for (int j = 0; j < S; j++) {
                float dj = subD[j];
                rank += (dj < d) || (dj == d && subI[j] < id);
            }
            if (rank < KNN) order[rank] = subSlot[s];
        }
    }
    __syncthreads();
    if (tid == 0) {
        double s0=0,s1=0,s2=0,s3=0,s4=0,s5=0,s6=0,s7=0,s8=0;
        for (int r = 0; r < KNN; r++) {
            int c = order[r];
            double X = (double)cX[c], Y = (double)cY[c], Z = (double)cZ[c];
            s0 += X; s1 += Y; s2 += Z;
            s3 += X*X; s4 += X*Y; s5 += X*Z;
            s6 += Y*Y; s7 += Y*Z; s8 += Z*Z;
        }
        const double K = (double)KNN;
        double mx = s0/K, my = s1/K, mz = s2/K;
        d_gcov[gb][0] = s3/K - mx*mx;
        d_gcov[gb][1] = s4/K - mx*my;
        d_gcov[gb][2] = s5/K - mx*mz;
        d_gcov[gb][3] = s6/K - my*my;
        d_gcov[gb][4] = s7/K - my*mz;
        d_gcov[gb][5] = s8/K - mz*mz;
    }
}

// ===========================================================================
// eig: 240 parallel 3x3 symmetric eigensolves
// ===========================================================================
__global__ void eig_kernel() {
    if (threadIdx.x != 0) return;
    const int t = blockIdx.x;

    double a00 = d_gcov[t][0], a01 = d_gcov[t][1], a02 = d_gcov[t][2];
    double a11 = d_gcov[t][3], a12 = d_gcov[t][4], a22 = d_gcov[t][5];

    double q  = (a00 + a11 + a22) / 3.0;
    double p1 = a01*a01 + a02*a02 + a12*a12;
    double b00 = a00 - q, b11 = a11 - q, b22 = a22 - q;
    double p2 = b00*b00 + b11*b11 + b22*b22 + 2.0*p1;
    double l1, l2, l3;
    if (p2 < 1e-60) {
        l1 = l2 = l3 = q;
    } else {
        double p  = sqrt(p2 / 6.0);
        double ip = 1.0 / p;
        double c00 = b00*ip, c11 = b11*ip, c22 = b22*ip;
        double c01 = a01*ip, c02 = a02*ip, c12 = a12*ip;
        double detB = c00*(c11*c22 - c12*c12)
                    - c01*(c01*c22 - c12*c02)
                    + c02*(c01*c12 - c11*c02);
        double r = 0.5 * detB;
        r = fmin(1.0, fmax(-1.0, r));
        double phi = (double)acosf((float)r) * (1.0/3.0);
        l3 = q + 2.0*p*(double)cosf((float)phi);
        l1 = q + 2.0*p*(double)cosf((float)(phi + 2.0943951023931953));
        l2 = 3.0*q - l1 - l3;
    }
    double denom = l1 + l2 + l3 + 1e-9;
    d_fs[t] = (l3 - l2) / denom;

    double r0x = a00 - l3, r0y = a01,      r0z = a02;
    double r1x = a01,      r1y = a11 - l3, r1z = a12;
    double r2x = a02,      r2y = a12,      r2z = a22 - l3;
    double vax = r0y*r1z - r0z*r1y, vay = r0z*r1x - r0x*r1z, vaz = r0x*r1y - r0y*r1x;
    double vbx = r1y*r2z - r1z*r2y, vby = r1z*r2x - r1x*r2z, vbz = r1x*r2y - r1y*r2x;
    double vcx = r2y*r0z - r2z*r0y, vcy = r2z*r0x - r2x*r0z, vcz = r2x*r0y - r2y*r0x;
    double na = vax*vax + vay*vay + vaz*vaz;
    double nb = vbx*vbx + vby*vby + vbz*vbz;
    double nc = vcx*vcx + vcy*vcy + vcz*vcz;
    double vx, vy, vz, nn;
    if (na >= nb && na >= nc) { vx = vax; vy = vay; vz = vaz; nn = na; }
    else if (nb >= nc)        { vx = vbx; vy = vby; vz = vbz; nn = nb; }
    else                      { vx = vcx; vy = vcy; vz = vcz; nn = nc; }
    if (nn < 1e-300) { vx = 0.0; vy = 0.0; vz = 1.0; nn = 1.0; }
    double inn = rsqrt(nn);
    d_dirs[t][0] = (float)(vx * inn);
    d_dirs[t][1] = (float)(vy * inn);
    d_dirs[t][2] = (float)(vz * inn);
}

// ===========================================================================
// out: nearest-group argmin + final reductions
// ===========================================================================
__global__ void __launch_bounds__(256) out_kernel(float* __restrict__ out) {
    __shared__ float  dirs[NGB][3];
    __shared__ float  gmf[NGB][3];
    __shared__ double redd[256];
    const int t = threadIdx.x;

    double fs = 0.0;
    if (t < NGB) {
        fs = d_fs[t];
        dirs[t][0] = d_dirs[t][0];
        dirs[t][1] = d_dirs[t][1];
        dirs[t][2] = d_dirs[t][2];
        gmf[t][0] = (float)d_gmean[t][0];
        gmf[t][1] = (float)d_gmean[t][1];
        gmf[t][2] = (float)d_gmean[t][2];
    }
    __syncthreads();

    double term = 0.0;
    if (t < NGB) {
        int b = t / NGRP, g = t % NGRP;
        float qx = gmf[t][0], qy = gmf[t][1], qz = gmf[t][2];
        float best = 3.4e38f; int bj = 0;
        for (int o = 0; o < NGRP; o++) {
            float dx = qx - gmf[b*NGRP+o][0];
            float dy = qy - gmf[b*NGRP+o][1];
            float dz = qz - gmf[b*NGRP+o][2];
            float dd = dx*dx + dy*dy + dz*dz;
            if (o == g) dd += 1e30f;
            if (dd < best) { best = dd; bj = o; }
        }
        int j = b*NGRP + bj;
        float cs = dirs[t][0]*dirs[j][0] + dirs[t][1]*dirs[j][1] + dirs[t][2]*dirs[j][2];
        term = 1.0 - (double)cs * (double)cs;
    }

    redd[t] = fs;
    __syncthreads();
    for (int s = 128; s > 0; s >>= 1) { if (t < s) redd[t] += redd[t+s]; __syncthreads(); }
    double sumfs = redd[0];
    __syncthreads();
    redd[t] = term;
    __syncthreads();
    for (int s = 128; s > 0; s >>= 1) { if (t < s) redd[t] += redd[t+s]; __syncthreads(); }
    double sumterm = redd[0];

    if (t == 0) out[0] = (float)(-sumfs / (double)NBATCH + sumterm / (double)NGB);
}

extern "C" void kernel_launch(void* const* d_in, const int* in_sizes, int n_in,
                              void* d_out, int out_size) {
    const float* pts = (const float*)d_in[0];
    float* out = (float*)d_out;
    cudaFuncSetAttribute(select_kernel, cudaFuncAttributeMaxDynamicSharedMemorySize, SEL_DYN);
    cudaFuncSetAttribute(rescue_select_kernel, cudaFuncAttributeMaxDynamicSharedMemorySize, RES_DYN);
    cudaFuncSetAttribute(fb_kernel, cudaFuncAttributeMaxDynamicSharedMemorySize, FB_DYN);
    prep_kernel<<<1, 256>>>(pts);
    scan_kernel<<<NBATCH*GT*PTC, NT>>>(pts);
    select_kernel<<<NGB, NT, SEL_DYN>>>(pts);
    rescue_scan_kernel<<<NGB*PTC, NT>>>(pts);
    rescue_select_kernel<<<NGB, NT, RES_DYN>>>();
    fb_kernel<<<NGB, NT, FB_DYN>>>(pts);
    eig_kernel<<<NGB, 32>>>();
    out_kernel<<<1, 256>>>(out);
}